// round 2
// baseline (speedup 1.0000x reference)
#include <cuda_runtime.h>

#define NN 100000
#define NE 3200000

// Scratch for per-node aggregation (allocation-free rule: __device__ global).
__device__ __align__(16) float g_aggr[(size_t)NN * 16];
// 1 if edge_index is int64, 0 if int32.
__device__ int g_idx64;

__global__ void detect_idx_kernel(const long long* __restrict__ ei64) {
    __shared__ int bad;
    if (threadIdx.x == 0) bad = 0;
    __syncthreads();
    // Sample 8192 values interpreted as int64. True int64 indices are in [0, NN).
    for (int i = threadIdx.x; i < 8192; i += blockDim.x) {
        long long v = ei64[i];
        if (v < 0 || v >= NN) bad = 1;
    }
    __syncthreads();
    if (threadIdx.x == 0) g_idx64 = bad ? 0 : 1;
}

__global__ void zero_aggr_kernel() {
    int i = blockIdx.x * blockDim.x + threadIdx.x;
    float4* p = (float4*)g_aggr;
    if (i < NN * 4) p[i] = make_float4(0.f, 0.f, 0.f, 0.f);
}

// One thread per edge: emb = W1 @ ea + b1; msg = relu(x[src] + emb);
// RED.v4 scatter-add into g_aggr[dst].
__global__ void edge_kernel(const float* __restrict__ x,
                            const void* __restrict__ ei_raw,
                            const float* __restrict__ ea,
                            const float* __restrict__ w1,
                            const float* __restrict__ b1) {
    __shared__ float sw[128];  // [16][8]
    __shared__ float sb[16];
    int t = threadIdx.x;
    if (t < 128) sw[t] = w1[t];
    if (t < 16)  sb[t] = b1[t];
    __syncthreads();

    int e = blockIdx.x * blockDim.x + t;
    if (e >= NE) return;

    long long s, d;
    if (g_idx64) {
        const long long* ei = (const long long*)ei_raw;
        s = __ldg(ei + e);
        d = __ldg(ei + NE + e);
    } else {
        const int* ei = (const int*)ei_raw;
        s = __ldg(ei + e);
        d = __ldg(ei + NE + e);
    }
    // Defensive clamp: never generate an out-of-bounds address.
    if (s < 0) s = 0; if (s >= NN) s = NN - 1;
    if (d < 0) d = 0; if (d >= NN) d = NN - 1;

    const float4* eap = (const float4*)(ea + (size_t)e * 8);
    float4 a0 = __ldg(eap);
    float4 a1 = __ldg(eap + 1);

    float m[16];
#pragma unroll
    for (int i = 0; i < 16; i++) {
        const float* w = sw + i * 8;
        m[i] = sb[i]
             + w[0]*a0.x + w[1]*a0.y + w[2]*a0.z + w[3]*a0.w
             + w[4]*a1.x + w[5]*a1.y + w[6]*a1.z + w[7]*a1.w;
    }

    const float4* xp = (const float4*)(x + (size_t)s * 16);
#pragma unroll
    for (int q = 0; q < 4; q++) {
        float4 xv = __ldg(xp + q);
        float r0 = fmaxf(m[4*q + 0] + xv.x, 0.f);
        float r1 = fmaxf(m[4*q + 1] + xv.y, 0.f);
        float r2 = fmaxf(m[4*q + 2] + xv.z, 0.f);
        float r3 = fmaxf(m[4*q + 3] + xv.w, 0.f);
        float* dst = g_aggr + (size_t)d * 16 + 4 * q;
        asm volatile("red.global.add.v4.f32 [%0], {%1,%2,%3,%4};"
                     :: "l"(dst), "f"(r0), "f"(r1), "f"(r2), "f"(r3)
                     : "memory");
    }
}

// One thread per node: out[n] = W2 @ (x[n] + aggr[n]) + b2
__global__ void node_kernel(const float* __restrict__ x,
                            const float* __restrict__ w2,
                            const float* __restrict__ b2,
                            float* __restrict__ out) {
    __shared__ float sw[512];  // [32][16]
    __shared__ float sb[32];
    int t = threadIdx.x;
    for (int i = t; i < 512; i += blockDim.x) sw[i] = w2[i];
    if (t < 32) sb[t] = b2[t];
    __syncthreads();

    int n = blockIdx.x * blockDim.x + t;
    if (n >= NN) return;

    float h[16];
    const float4* xp = (const float4*)(x + (size_t)n * 16);
    const float4* ap = (const float4*)(g_aggr + (size_t)n * 16);
#pragma unroll
    for (int q = 0; q < 4; q++) {
        float4 xv = __ldg(xp + q);
        float4 av = ap[q];
        h[4*q + 0] = xv.x + av.x;
        h[4*q + 1] = xv.y + av.y;
        h[4*q + 2] = xv.z + av.z;
        h[4*q + 3] = xv.w + av.w;
    }

    float4* op = (float4*)(out + (size_t)n * 32);
#pragma unroll
    for (int o = 0; o < 32; o += 4) {
        float acc[4];
#pragma unroll
        for (int j = 0; j < 4; j++) {
            const float* w = sw + (o + j) * 16;
            float s = sb[o + j];
#pragma unroll
            for (int k = 0; k < 16; k++) s += w[k] * h[k];
            acc[j] = s;
        }
        op[o / 4] = make_float4(acc[0], acc[1], acc[2], acc[3]);
    }
}

extern "C" void kernel_launch(void* const* d_in, const int* in_sizes, int n_in,
                              void* d_out, int out_size) {
    // metadata order: x, edge_index, edge_attr, lin1_w, lin1_b, nn_w, nn_b
    const float* x   = (const float*)d_in[0];
    const void*  ei  = d_in[1];
    const float* ea  = (const float*)d_in[2];
    const float* w1  = (const float*)d_in[3];
    const float* b1  = (const float*)d_in[4];
    const float* w2  = (const float*)d_in[5];
    const float* b2  = (const float*)d_in[6];
    float*       out = (float*)d_out;

    detect_idx_kernel<<<1, 256>>>((const long long*)ei);
    zero_aggr_kernel<<<(NN * 4 + 255) / 256, 256>>>();
    edge_kernel<<<(NE + 255) / 256, 256>>>(x, ei, ea, w1, b1);
    node_kernel<<<(NN + 255) / 256, 256>>>(x, w2, b2, out);
}